// round 3
// baseline (speedup 1.0000x reference)
#include <cuda_runtime.h>
#include <cstddef>
#include <cstdint>

// Problem constants (fixed by the dataset)
#define N_NODES 50000
#define N_EDGES 800000
#define IN_DIM 128

// ---------------------------------------------------------------------------
// Scratch: single static __device__ arena (allocation-free rule)
// ---------------------------------------------------------------------------
constexpr size_t alup(size_t x) { return (x + 255) & ~(size_t)255; }
constexpr size_t OFF_FEAT   = 0;                                                  // N*256 f32
constexpr size_t OFF_RESID  = alup(OFF_FEAT   + (size_t)N_NODES * 256 * 4);       // N*256 f32
constexpr size_t OFF_XA     = alup(OFF_RESID  + (size_t)N_NODES * 256 * 4);       // N*128 f32
constexpr size_t OFF_XB     = alup(OFF_XA     + (size_t)N_NODES * 128 * 4);       // N*128 f32
constexpr size_t OFF_EL     = alup(OFF_XB     + (size_t)N_NODES * 128 * 4);       // N*4 f32
constexpr size_t OFF_ER     = alup(OFF_EL     + (size_t)N_NODES * 4 * 4);         // N*4 f32
constexpr size_t OFF_ROWPTR = alup(OFF_ER     + (size_t)N_NODES * 4 * 4);         // (N+1) i32
constexpr size_t OFF_CURSOR = alup(OFF_ROWPTR + (size_t)(N_NODES + 1) * 4);       // N i32
constexpr size_t OFF_DEG    = alup(OFF_CURSOR + (size_t)N_NODES * 4);             // N i32
constexpr size_t OFF_CSRC   = alup(OFF_DEG    + (size_t)N_NODES * 4);             // E i32
constexpr size_t SCRATCH_TOTAL = alup(OFF_CSRC + (size_t)N_EDGES * 4);

__device__ __align__(256) unsigned char g_scratch[SCRATCH_TOTAL];

__device__ __forceinline__ float lrelu(float x) { return x >= 0.f ? x : 0.2f * x; }

// ---------------------------------------------------------------------------
// CSR build: zero -> histogram -> scan -> scatter
// ---------------------------------------------------------------------------
__global__ void zero_int_kernel(int* p, int n) {
    int i = blockIdx.x * blockDim.x + threadIdx.x;
    if (i < n) p[i] = 0;
}

__global__ void hist_kernel(const int* __restrict__ dst, int* __restrict__ deg, int e) {
    int i = blockIdx.x * blockDim.x + threadIdx.x;
    if (i < e) atomicAdd(&deg[dst[i]], 1);
}

// Single-block exclusive scan over deg[0..n): row_ptr[i+1] = incl, cursor[i] = excl
__global__ void scan_kernel(const int* __restrict__ deg, int* __restrict__ row_ptr,
                            int* __restrict__ cursor, int n) {
    __shared__ int warp_sums[32];
    __shared__ int s_carry;
    int t = threadIdx.x;  // 1024 threads
    if (t == 0) { s_carry = 0; row_ptr[0] = 0; }
    __syncthreads();
    for (int base = 0; base < n; base += 1024) {
        int i = base + t;
        int v = (i < n) ? deg[i] : 0;
        int x = v;
        #pragma unroll
        for (int o = 1; o < 32; o <<= 1) {
            int y = __shfl_up_sync(0xffffffffu, x, o);
            if ((t & 31) >= o) x += y;
        }
        if ((t & 31) == 31) warp_sums[t >> 5] = x;
        __syncthreads();
        if (t < 32) {
            int w = warp_sums[t];
            #pragma unroll
            for (int o = 1; o < 32; o <<= 1) {
                int y = __shfl_up_sync(0xffffffffu, w, o);
                if (t >= o) w += y;
            }
            warp_sums[t] = w;
        }
        __syncthreads();
        int incl = x + ((t >= 32) ? warp_sums[(t >> 5) - 1] : 0);
        int total = warp_sums[31];
        if (i < n) {
            row_ptr[i + 1] = s_carry + incl;
            cursor[i]      = s_carry + incl - v;
        }
        __syncthreads();
        if (t == 0) s_carry += total;
        __syncthreads();
    }
}

__global__ void scatter_kernel(const int* __restrict__ src, const int* __restrict__ dst,
                               int* __restrict__ cursor, int* __restrict__ csrc, int e) {
    int i = blockIdx.x * blockDim.x + threadIdx.x;
    if (i < e) {
        int p = atomicAdd(&cursor[dst[i]], 1);
        csrc[p] = src[i];
    }
}

// ---------------------------------------------------------------------------
// GEMM: Y[n, M] = X[n, 128] @ W[128, M].  64x128 tile, 256 threads, 4x8/thread.
// ---------------------------------------------------------------------------
__global__ __launch_bounds__(256) void gemm_kernel(
    const float* __restrict__ X, const float* __restrict__ W,
    float* __restrict__ Y, int n, int Mcols) {
    __shared__ float Xs[16][64];
    __shared__ float Ws[16][128];
    int tid = threadIdx.x;
    int tx = tid & 15, ty = tid >> 4;
    int r0 = blockIdx.x * 64, c0 = blockIdx.y * 128;
    int Wld = Mcols >> 2;  // float4 row stride
    float acc[4][8];
    #pragma unroll
    for (int i = 0; i < 4; i++)
        #pragma unroll
        for (int j = 0; j < 8; j++) acc[i][j] = 0.f;

    for (int k0 = 0; k0 < 128; k0 += 16) {
        {   // X tile (transposed into Xs[k][row])
            int row = tid >> 2, kq = tid & 3;
            int r = r0 + row;
            float4 xv = make_float4(0.f, 0.f, 0.f, 0.f);
            if (r < n) xv = reinterpret_cast<const float4*>(X)[(size_t)r * 32 + (k0 >> 2) + kq];
            Xs[kq * 4 + 0][row] = xv.x;
            Xs[kq * 4 + 1][row] = xv.y;
            Xs[kq * 4 + 2][row] = xv.z;
            Xs[kq * 4 + 3][row] = xv.w;
        }
        {   // W tile
            int kk = tid >> 4, c4 = tid & 15;
            const float4* W4 = reinterpret_cast<const float4*>(W);
            float4 w0 = W4[(size_t)(k0 + kk) * Wld + (c0 >> 2) + c4];
            float4 w1 = W4[(size_t)(k0 + kk) * Wld + (c0 >> 2) + c4 + 16];
            reinterpret_cast<float4*>(&Ws[kk][0])[c4]      = w0;
            reinterpret_cast<float4*>(&Ws[kk][0])[c4 + 16] = w1;
        }
        __syncthreads();
        #pragma unroll
        for (int kk = 0; kk < 16; kk++) {
            float4 a  = reinterpret_cast<float4*>(&Xs[kk][0])[ty];
            float4 b0 = reinterpret_cast<float4*>(&Ws[kk][0])[tx];
            float4 b1 = reinterpret_cast<float4*>(&Ws[kk][0])[tx + 16];
            float av[4] = {a.x, a.y, a.z, a.w};
            float bv[8] = {b0.x, b0.y, b0.z, b0.w, b1.x, b1.y, b1.z, b1.w};
            #pragma unroll
            for (int i = 0; i < 4; i++)
                #pragma unroll
                for (int j = 0; j < 8; j++) acc[i][j] += av[i] * bv[j];
        }
        __syncthreads();
    }
    #pragma unroll
    for (int i = 0; i < 4; i++) {
        int r = r0 + ty * 4 + i;
        if (r < n) {
            float4 o0 = make_float4(acc[i][0], acc[i][1], acc[i][2], acc[i][3]);
            float4 o1 = make_float4(acc[i][4], acc[i][5], acc[i][6], acc[i][7]);
            float4* Y4 = reinterpret_cast<float4*>(Y);
            Y4[(size_t)r * Wld + (c0 >> 2) + tx]      = o0;
            Y4[(size_t)r * Wld + (c0 >> 2) + tx + 16] = o1;
        }
    }
}

// ---------------------------------------------------------------------------
// Attention coefficients: el[n,h] = sum_d feat[n,h,d]*al[h,d] (and er)
// ---------------------------------------------------------------------------
__global__ void attn32_kernel(const float* __restrict__ feat, const float* __restrict__ al,
                              const float* __restrict__ ar, float* __restrict__ el,
                              float* __restrict__ er) {
    int nid = blockIdx.x;
    int t = threadIdx.x;  // 128
    float f = feat[(size_t)nid * 128 + t];
    float pl = f * al[t];
    float pr = f * ar[t];
    #pragma unroll
    for (int o = 16; o; o >>= 1) {
        pl += __shfl_xor_sync(0xffffffffu, pl, o);
        pr += __shfl_xor_sync(0xffffffffu, pr, o);
    }
    if ((t & 31) == 0) {
        el[nid * 4 + (t >> 5)] = pl;
        er[nid * 4 + (t >> 5)] = pr;
    }
}

__global__ void attn64_kernel(const float* __restrict__ feat, const float* __restrict__ al,
                              const float* __restrict__ ar, float* __restrict__ el,
                              float* __restrict__ er) {
    __shared__ float sl[8], sr[8];
    int nid = blockIdx.x;
    int t = threadIdx.x;  // 256
    float f = feat[(size_t)nid * 256 + t];
    float pl = f * al[t];
    float pr = f * ar[t];
    #pragma unroll
    for (int o = 16; o; o >>= 1) {
        pl += __shfl_xor_sync(0xffffffffu, pl, o);
        pr += __shfl_xor_sync(0xffffffffu, pr, o);
    }
    int w = t >> 5;
    if ((t & 31) == 0) { sl[w] = pl; sr[w] = pr; }
    __syncthreads();
    if (t < 4) {
        el[nid * 4 + t] = sl[2 * t] + sl[2 * t + 1];
        er[nid * 4 + t] = sr[2 * t] + sr[2 * t + 1];
    }
}

// ---------------------------------------------------------------------------
// Fused edge-softmax + aggregation + residual + activation.
// One warp per destination node. No atomics.
//   D: per-head out dim (32 or 64). RELU: apply relu. MEAN: mean over heads (L3).
// ---------------------------------------------------------------------------
#define AGG_CAP 96

template <int D, bool RELU, bool MEAN>
__global__ __launch_bounds__(256) void agg_kernel(
    const float* __restrict__ feat, const float* __restrict__ el,
    const float* __restrict__ er, const int* __restrict__ row_ptr,
    const int* __restrict__ csrc, const float* __restrict__ resid,
    float* __restrict__ out, int n) {
    __shared__ float4 sx[8][AGG_CAP];
    int warp = (blockIdx.x * blockDim.x + threadIdx.x) >> 5;
    int lane = threadIdx.x & 31;
    int wslot = threadIdx.x >> 5;
    if (warp >= n) return;

    int e0 = row_ptr[warp], e1 = row_ptr[warp + 1];
    float4 erd = reinterpret_cast<const float4*>(er)[warp];

    // ---- pass 1: per-head max over incoming edges
    float m0 = -1e30f, m1 = -1e30f, m2 = -1e30f, m3 = -1e30f;
    for (int i = e0 + lane; i < e1; i += 32) {
        int s = csrc[i];
        float4 e4 = reinterpret_cast<const float4*>(el)[s];
        m0 = fmaxf(m0, lrelu(e4.x + erd.x));
        m1 = fmaxf(m1, lrelu(e4.y + erd.y));
        m2 = fmaxf(m2, lrelu(e4.z + erd.z));
        m3 = fmaxf(m3, lrelu(e4.w + erd.w));
    }
    #pragma unroll
    for (int o = 16; o; o >>= 1) {
        m0 = fmaxf(m0, __shfl_xor_sync(0xffffffffu, m0, o));
        m1 = fmaxf(m1, __shfl_xor_sync(0xffffffffu, m1, o));
        m2 = fmaxf(m2, __shfl_xor_sync(0xffffffffu, m2, o));
        m3 = fmaxf(m3, __shfl_xor_sync(0xffffffffu, m3, o));
    }

    // ---- pass 2: exp + sum (stage exp values in smem up to AGG_CAP)
    float s0 = 0.f, s1 = 0.f, s2 = 0.f, s3 = 0.f;
    for (int i = e0 + lane; i < e1; i += 32) {
        int s = csrc[i];
        float4 e4 = reinterpret_cast<const float4*>(el)[s];
        float4 ex;
        ex.x = __expf(lrelu(e4.x + erd.x) - m0);
        ex.y = __expf(lrelu(e4.y + erd.y) - m1);
        ex.z = __expf(lrelu(e4.z + erd.z) - m2);
        ex.w = __expf(lrelu(e4.w + erd.w) - m3);
        int li = i - e0;
        if (li < AGG_CAP) sx[wslot][li] = ex;
        s0 += ex.x; s1 += ex.y; s2 += ex.z; s3 += ex.w;
    }
    #pragma unroll
    for (int o = 16; o; o >>= 1) {
        s0 += __shfl_xor_sync(0xffffffffu, s0, o);
        s1 += __shfl_xor_sync(0xffffffffu, s1, o);
        s2 += __shfl_xor_sync(0xffffffffu, s2, o);
        s3 += __shfl_xor_sync(0xffffffffu, s3, o);
    }
    float i0 = 1.f / s0, i1 = 1.f / s1, i2 = 1.f / s2, i3 = 1.f / s3;
    __syncwarp();

    // ---- pass 3: weighted aggregation (all lanes walk edges together)
    constexpr int J = D / 32;
    float acc[4 * J];
    #pragma unroll
    for (int q = 0; q < 4 * J; q++) acc[q] = 0.f;

    for (int i = e0; i < e1; ++i) {
        int s = csrc[i];
        float4 a;
        int li = i - e0;
        if (li < AGG_CAP) {
            a = sx[wslot][li];
        } else {
            float4 e4 = reinterpret_cast<const float4*>(el)[s];
            a.x = __expf(lrelu(e4.x + erd.x) - m0);
            a.y = __expf(lrelu(e4.y + erd.y) - m1);
            a.z = __expf(lrelu(e4.z + erd.z) - m2);
            a.w = __expf(lrelu(e4.w + erd.w) - m3);
        }
        a.x *= i0; a.y *= i1; a.z *= i2; a.w *= i3;
        const float* fr = feat + (size_t)s * (4 * D);
        #pragma unroll
        for (int j = 0; j < J; j++) {
            acc[0 * J + j] += a.x * fr[0 * D + j * 32 + lane];
            acc[1 * J + j] += a.y * fr[1 * D + j * 32 + lane];
            acc[2 * J + j] += a.z * fr[2 * D + j * 32 + lane];
            acc[3 * J + j] += a.w * fr[3 * D + j * 32 + lane];
        }
    }

    // ---- epilogue: residual (+ activation / head-mean)
    const float* rr = resid + (size_t)warp * (4 * D);
    if (!MEAN) {
        #pragma unroll
        for (int h = 0; h < 4; h++) {
            #pragma unroll
            for (int j = 0; j < J; j++) {
                float v = acc[h * J + j] + rr[h * D + j * 32 + lane];
                if (RELU) v = fmaxf(v, 0.f);
                out[(size_t)warp * (4 * D) + h * D + j * 32 + lane] = v;
            }
        }
    } else {
        #pragma unroll
        for (int j = 0; j < J; j++) {
            float v = 0.f;
            #pragma unroll
            for (int h = 0; h < 4; h++) v += acc[h * J + j] + rr[h * D + j * 32 + lane];
            out[(size_t)warp * D + j * 32 + lane] = 0.25f * v;
        }
    }
}

// ---------------------------------------------------------------------------
// Host launcher
// ---------------------------------------------------------------------------
extern "C" void kernel_launch(void* const* d_in, const int* in_sizes, int n_in,
                              void* d_out, int out_size) {
    const float* h     = (const float*)d_in[0];
    const float* W1    = (const float*)d_in[1];
    const float* al1   = (const float*)d_in[2];
    const float* ar1   = (const float*)d_in[3];
    const float* W2    = (const float*)d_in[4];
    const float* al2   = (const float*)d_in[5];
    const float* ar2   = (const float*)d_in[6];
    const float* W3    = (const float*)d_in[7];
    const float* al3   = (const float*)d_in[8];
    const float* ar3   = (const float*)d_in[9];
    const float* resW3 = (const float*)d_in[10];
    const int*   src   = (const int*)d_in[11];
    const int*   dst   = (const int*)d_in[12];
    float*       out   = (float*)d_out;

    int n = in_sizes[0] / IN_DIM;   // 50000
    int e = in_sizes[11];           // 800000

    unsigned char* base = nullptr;
    cudaGetSymbolAddress((void**)&base, g_scratch);
    float* feat   = (float*)(base + OFF_FEAT);
    float* resid  = (float*)(base + OFF_RESID);
    float* xA     = (float*)(base + OFF_XA);
    float* xB     = (float*)(base + OFF_XB);
    float* el     = (float*)(base + OFF_EL);
    float* er     = (float*)(base + OFF_ER);
    int*   rowptr = (int*)(base + OFF_ROWPTR);
    int*   cursor = (int*)(base + OFF_CURSOR);
    int*   deg    = (int*)(base + OFF_DEG);
    int*   csrc   = (int*)(base + OFF_CSRC);

    // --- CSR build (same graph for all layers) ---
    zero_int_kernel<<<(n + 255) / 256, 256>>>(deg, n);
    hist_kernel<<<(e + 255) / 256, 256>>>(dst, deg, e);
    scan_kernel<<<1, 1024>>>(deg, rowptr, cursor, n);
    scatter_kernel<<<(e + 255) / 256, 256>>>(src, dst, cursor, csrc, e);

    int gemm_rows = (n + 63) / 64;
    int agg_blocks = (n + 7) / 8;

    // --- Layer 1 (D=32, relu, residual = h) ---
    gemm_kernel<<<dim3(gemm_rows, 1), 256>>>(h, W1, feat, n, 128);
    attn32_kernel<<<n, 128>>>(feat, al1, ar1, el, er);
    agg_kernel<32, true, false><<<agg_blocks, 256>>>(feat, el, er, rowptr, csrc, h, xA, n);

    // --- Layer 2 (D=32, relu, residual = xA) ---
    gemm_kernel<<<dim3(gemm_rows, 1), 256>>>(xA, W2, feat, n, 128);
    attn32_kernel<<<n, 128>>>(feat, al2, ar2, el, er);
    agg_kernel<32, true, false><<<agg_blocks, 256>>>(feat, el, er, rowptr, csrc, xA, xB, n);

    // --- Layer 3 (D=64, residual = xB @ resW3, head-mean output) ---
    gemm_kernel<<<dim3(gemm_rows, 2), 256>>>(xB, W3, feat, n, 256);
    gemm_kernel<<<dim3(gemm_rows, 2), 256>>>(xB, resW3, resid, n, 256);
    attn64_kernel<<<n, 256>>>(feat, al3, ar3, el, er);
    agg_kernel<64, false, true><<<agg_blocks, 256>>>(feat, el, er, rowptr, csrc, resid, out, n);
}